// round 4
// baseline (speedup 1.0000x reference)
#include <cuda_runtime.h>

#define NB 512
#define NG 100
#define NP 100
#define NE 128
#define NH 8
#define NKD 16
#define LDP 132     // padded row stride for [100][128]-ish tiles (floats)
#define LDW 132     // WT row stride
#define LDK 102     // kT row stride (even -> aligned u64 pair loads; 2-way store conflict only)
#define LDS_S 104   // staged score row stride
#define NTHR 512

typedef unsigned long long u64;

__device__ __forceinline__ void fma2(u64& d, u64 a, u64 b) {
    asm("fma.rn.f32x2 %0, %1, %2, %0;" : "+l"(d) : "l"(a), "l"(b));
}
__device__ __forceinline__ u64 add2(u64 a, u64 b) {
    u64 d; asm("add.rn.f32x2 %0, %1, %2;" : "=l"(d) : "l"(a), "l"(b)); return d;
}
__device__ __forceinline__ u64 pk(float lo, float hi) {
    u64 d; asm("mov.b64 %0, {%1, %2};" : "=l"(d) : "f"(lo), "f"(hi)); return d;
}
__device__ __forceinline__ void unpk(u64 a, float& lo, float& hi) {
    asm("mov.b64 {%0, %1}, %2;" : "=f"(lo), "=f"(hi) : "l"(a));
}
__device__ __forceinline__ float f2sum(u64 a) {
    float lo, hi; unpk(a, lo, hi); return lo + hi;
}

// Transpose 128x128 weight into smem WT[n][e]=W[e][n].
// float4-gather over e, STS.128 (row stride 528B == 16 mod 128 -> conflict-free).
__device__ __forceinline__ void fillWT(const float* __restrict__ W,
                                       float* __restrict__ WT, int t) {
    int n  = t & 127;
    int eb = t >> 7;                 // 0..3
    #pragma unroll
    for (int pass = 0; pass < 8; ++pass) {
        int e = eb * 32 + pass * 4;
        float4 v;
        v.x = __ldg(W + (e + 0) * NE + n);
        v.y = __ldg(W + (e + 1) * NE + n);
        v.z = __ldg(W + (e + 2) * NE + n);
        v.w = __ldg(W + (e + 3) * NE + n);
        *(float4*)(WT + n * LDW + e) = v;
    }
}

// acc[i] += A[mg*25+i][:] . WT[n][:], e-len 128, f32x2 e-packed.
// Per e4: 1 vector W load + 25 broadcasts + 50 FFMA2.
__device__ __forceinline__ void gemm25(const float* __restrict__ A,
                                       const float* __restrict__ WT,
                                       u64 (&acc)[25], int n, int mg) {
    const ulonglong2* wp = (const ulonglong2*)(WT + n * LDW);
    const float* arow = A + mg * 25 * LDP;
    #pragma unroll 2
    for (int e4 = 0; e4 < 32; ++e4) {
        ulonglong2 w = wp[e4];
        #pragma unroll
        for (int i = 0; i < 25; ++i) {
            ulonglong2 a = *(const ulonglong2*)(arow + i * LDP + e4 * 4);
            fma2(acc[i], a.x, w.x);
            fma2(acc[i], a.y, w.y);
        }
    }
}

__global__ __launch_bounds__(NTHR, 1)
void fused_attn_kernel(
    const float* __restrict__ in1, const float* __restrict__ in2,
    const float* __restrict__ rem, const float* __restrict__ mask,
    const float* __restrict__ enc, const float* __restrict__ Wq,
    const float* __restrict__ Wk, const float* __restrict__ Wv,
    const float* __restrict__ Wc, const float* __restrict__ bc,
    float* __restrict__ out)
{
    extern __shared__ float sm[];
    // [0,13200)      s_enc  (live to the end; rows>=100 read as garbage, discarded)
    // [13200,26400)  s_k    region: WT alias (spills to 30096) / kT / mh
    // [26400,29728)  s_ws   16x208 per-warp attention-weight slots
    // [29728,29856)  s_q0
    // [30112,43312)  s_v    (later: staged pointer scores)
    // [43312,56512)  s_q    (input2 -> q -> out_concat)
    float* s_enc = sm;
    float* s_k   = sm + 13200;
    float* s_ws  = sm + 26400;
    float* s_q0  = sm + 29728;
    float* s_v   = sm + 30112;
    float* s_q   = sm + 43312;
    float* s_wt  = s_k;              // alias
    float* s_kT  = s_k;              // alias (128 x 102 = 13056)
    float* s_sc  = s_v;              // alias (100 x 104 = 10400)

    const int b    = blockIdx.x;
    const int t    = threadIdx.x;
    const int lane = t & 31;
    const int warp = t >> 5;
    const int mg   = warp >> 2;          // row group (25 rows)
    const int n    = (warp & 3) * 32 + lane;   // column owned in GEMMs

    const float* encb  = enc  + (size_t)b * NP * NE;
    const float* in2b  = in2  + (size_t)b * NG * NE;
    const float* maskb = mask + (size_t)b * NG * NP;

    u64 acc[25];

    // ---------------- Phase 1: stage enc + input2, compute q0 ----------------
    for (int idx = t; idx < NP * NE; idx += NTHR)
        s_enc[(idx >> 7) * LDP + (idx & 127)] = encb[idx];
    for (int idx = t; idx < NG * NE; idx += NTHR)
        s_q[(idx >> 7) * LDP + (idx & 127)] = in2b[idx];
    if (t < NE) {
        const float* i1 = in1 + (size_t)b * NE;
        float s = 0.f;
        #pragma unroll 8
        for (int e = 0; e < NE; ++e) s += i1[e] * __ldg(Wq + e * NE + t);
        s_q0[t] = s;
    }
    __syncthreads();                              // S1

    // ---------------- q-pass: q = [in1 | in2 | rem] @ Wq ----------------
    {
        float rq0 = s_q0[n];
        float rwl = __ldg(Wq + 2 * NE * NE + n);  // last row (rem weight)
        __syncthreads();                          // S2: q0 reads done before WT spill
        fillWT(Wq + NE * NE, s_wt, t);            // rows 128..255 (input2 part)
        __syncthreads();                          // S3
        #pragma unroll
        for (int i = 0; i < 25; ++i) acc[i] = 0ull;
        gemm25(s_q, s_wt, acc, n, mg);
        __syncthreads();                          // S4: WT + input2 reads done
        const float* remb = rem + (size_t)b * NG;
        #pragma unroll
        for (int i = 0; i < 25; ++i) {
            int m = mg * 25 + i;
            s_q[m * LDP + n] = f2sum(acc[i]) + rq0 + __ldg(remb + m) * rwl;
        }
    }

    // ---------------- v-pass: v = enc @ Wv ----------------
    fillWT(Wv, s_wt, t);                          // WT reads finished at S4
    __syncthreads();                              // S5
    #pragma unroll
    for (int i = 0; i < 25; ++i) acc[i] = 0ull;
    gemm25(s_enc, s_wt, acc, n, mg);
    #pragma unroll
    for (int i = 0; i < 25; ++i)
        s_v[(mg * 25 + i) * LDP + n] = f2sum(acc[i]);
    __syncthreads();                              // S6

    // ---------------- k-pass: kT[n][m] = (enc @ Wk)^T ----------------
    fillWT(Wk, s_wt, t);
    __syncthreads();                              // S7
    #pragma unroll
    for (int i = 0; i < 25; ++i) acc[i] = 0ull;
    gemm25(s_enc, s_wt, acc, n, mg);
    __syncthreads();                              // S8: WT reads done before kT overwrites
    #pragma unroll
    for (int i = 0; i < 25; ++i)
        s_kT[n * LDK + (mg * 25 + i)] = f2sum(acc[i]);
    __syncthreads();                              // S9

    // ---------------- Phase 4: multi-head attention (4 g x head per task) ----
    for (int task = warp; task < (NG / 4) * NH; task += 16) {
        int h  = task & 7;
        int gb = (task >> 3) * 4;
        const float* kTh = s_kT + (h * NKD) * LDK;

        // QK: p-packed scores; lane owns p = {2l,2l+1} and {64+2l,65+2l}
        u64 a0[4] = {0,0,0,0}, a1[4] = {0,0,0,0};
        #pragma unroll
        for (int e0 = 0; e0 < NKD; e0 += 4) {
            float4 qf[4];
            #pragma unroll
            for (int g = 0; g < 4; ++g)
                qf[g] = *(const float4*)(s_q + (gb + g) * LDP + h * NKD + e0);
            #pragma unroll
            for (int e = 0; e < 4; ++e) {
                const float* kr = kTh + (e0 + e) * LDK;
                u64 k0 = *(const u64*)(kr + 2 * lane);
                u64 k1 = *(const u64*)(kr + 64 + 2 * lane);
                #pragma unroll
                for (int g = 0; g < 4; ++g) {
                    float qv = (e == 0) ? qf[g].x : (e == 1) ? qf[g].y
                             : (e == 2) ? qf[g].z : qf[g].w;
                    u64 q2 = pk(qv, qv);
                    fma2(a0[g], q2, k0);
                    fma2(a1[g], q2, k1);
                }
            }
        }

        // softmax per g (4 scores per lane)
        float w[4][4];
        #pragma unroll
        for (int g = 0; g < 4; ++g) {
            int gi = gb + g;
            float x0, x1, x2, x3;
            unpk(a0[g], x0, x1);
            unpk(a1[g], x2, x3);
            float2 mA = *(const float2*)(maskb + gi * NP + 2 * lane);
            x0 = x0 * 0.25f + mA.x;
            x1 = x1 * 0.25f + mA.y;
            if (lane < 18) {
                float2 mB = *(const float2*)(maskb + gi * NP + 64 + 2 * lane);
                x2 = x2 * 0.25f + mB.x;
                x3 = x3 * 0.25f + mB.y;
            } else { x2 = -3e38f; x3 = -3e38f; }
            float mx = fmaxf(fmaxf(x0, x1), fmaxf(x2, x3));
            #pragma unroll
            for (int o = 16; o; o >>= 1)
                mx = fmaxf(mx, __shfl_xor_sync(0xffffffffu, mx, o));
            x0 = __expf(x0 - mx);
            x1 = __expf(x1 - mx);
            x2 = (lane < 18) ? __expf(x2 - mx) : 0.f;
            x3 = (lane < 18) ? __expf(x3 - mx) : 0.f;
            float sum = x0 + x1 + x2 + x3;
            #pragma unroll
            for (int o = 16; o; o >>= 1)
                sum += __shfl_xor_sync(0xffffffffu, sum, o);
            float inv = 1.f / sum;
            w[g][0] = x0 * inv; w[g][1] = x1 * inv;
            w[g][2] = x2 * inv; w[g][3] = x3 * inv;
        }

        // AV in 2 sub-batches of 2 g using the per-warp ws slot
        float* wsl = s_ws + warp * 208;
        int c4 = lane >> 3, pgl = lane & 7;
        #pragma unroll
        for (int sb = 0; sb < 2; ++sb) {
            int ga = 2 * sb, gbd = 2 * sb + 1;
            float* w0 = wsl;
            float* w1 = wsl + 104;
            *(float2*)(w0 + 2 * lane) = make_float2(w[ga][0], w[ga][1]);
            *(float2*)(w1 + 2 * lane) = make_float2(w[gbd][0], w[gbd][1]);
            if (lane < 18) {
                *(float2*)(w0 + 64 + 2 * lane) = make_float2(w[ga][2], w[ga][3]);
                *(float2*)(w1 + 64 + 2 * lane) = make_float2(w[gbd][2], w[gbd][3]);
            }
            __syncwarp();
            u64 o00 = 0, o01 = 0, o10 = 0, o11 = 0;
            #pragma unroll
            for (int pp = 0; pp < 13; ++pp) {
                int p = pgl + 8 * pp;
                if (p < NP) {
                    ulonglong2 vv = *((const ulonglong2*)(s_v + p * LDP + h * NKD) + c4);
                    u64 aa = pk(w0[p], w0[p]);
                    u64 cc = pk(w1[p], w1[p]);
                    fma2(o00, aa, vv.x); fma2(o01, aa, vv.y);
                    fma2(o10, cc, vv.x); fma2(o11, cc, vv.y);
                }
            }
            #pragma unroll
            for (int o = 4; o; o >>= 1) {
                o00 = add2(o00, __shfl_xor_sync(0xffffffffu, o00, o));
                o01 = add2(o01, __shfl_xor_sync(0xffffffffu, o01, o));
                o10 = add2(o10, __shfl_xor_sync(0xffffffffu, o10, o));
                o11 = add2(o11, __shfl_xor_sync(0xffffffffu, o11, o));
            }
            if (pgl == 0) {
                ulonglong2 r0; r0.x = o00; r0.y = o01;
                ulonglong2 r1; r1.x = o10; r1.y = o11;
                *((ulonglong2*)(s_q + (gb + ga)  * LDP + h * NKD + 4 * c4)) = r0;
                *((ulonglong2*)(s_q + (gb + gbd) * LDP + h * NKD + 4 * c4)) = r1;
            }
            __syncwarp();
        }
    }
    __syncthreads();                              // S10

    // ---------------- Phase 5: mh = out_concat @ Wc + bc -> s_k -------------
    fillWT(Wc, s_wt, t);                          // clobbers kT + ws + q0 (all dead)
    __syncthreads();                              // S11
    {
        float rbc = __ldg(bc + n);
        #pragma unroll
        for (int i = 0; i < 25; ++i) acc[i] = 0ull;
        gemm25(s_q, s_wt, acc, n, mg);
        __syncthreads();                          // S12: WT reads done before mh overwrites
        #pragma unroll
        for (int i = 0; i < 25; ++i)
            s_k[(mg * 25 + i) * LDP + n] = f2sum(acc[i]) + rbc;
    }
    __syncthreads();                              // S13

    // ---------------- Phase 6a: raw pointer scores -> s_sc ------------------
    {
        // same warp tiling: "column" = p (up to 127; >=100 discarded)
        #pragma unroll
        for (int i = 0; i < 25; ++i) acc[i] = 0ull;
        gemm25(s_k, s_enc, acc, n, mg);           // A = mh rows, B rows indexed by p=n
        if (n < NP) {
            #pragma unroll
            for (int i = 0; i < 25; ++i)
                s_sc[(mg * 25 + i) * LDS_S + n] = f2sum(acc[i]);
        }
    }
    __syncthreads();                              // S14

    // ---------------- Phase 6b: tanh clip + softmax + output ----------------
    const float invsq = 0.08838834764831845f;     // 1/sqrt(128)
    float* outb = out + (size_t)b * NG * NP;
    for (int g = warp; g < NG; g += 16) {
        float sc[4]; float mx = -3e38f;
        #pragma unroll
        for (int r = 0; r < 4; ++r) {
            int p = lane + 32 * r;
            float s = -3e38f;
            if (p < NP)
                s = 10.f * tanhf(s_sc[g * LDS_S + p] * invsq) + __ldg(maskb + g * NP + p);
            sc[r] = s; mx = fmaxf(mx, s);
        }
        #pragma unroll
        for (int o = 16; o; o >>= 1)
            mx = fmaxf(mx, __shfl_xor_sync(0xffffffffu, mx, o));
        float sum = 0.f;
        #pragma unroll
        for (int r = 0; r < 4; ++r) {
            float e_ = (sc[r] > -1e37f) ? __expf(sc[r] - mx) : 0.f;
            sc[r] = e_; sum += e_;
        }
        #pragma unroll
        for (int o = 16; o; o >>= 1)
            sum += __shfl_xor_sync(0xffffffffu, sum, o);
        float inv = 1.f / sum;
        #pragma unroll
        for (int r = 0; r < 4; ++r) {
            int p = lane + 32 * r;
            if (p < NP) outb[g * NP + p] = sc[r] * inv;
        }
    }
}

extern "C" void kernel_launch(void* const* d_in, const int* in_sizes, int n_in,
                              void* d_out, int out_size)
{
    const float* in1  = (const float*)d_in[0];
    const float* in2  = (const float*)d_in[1];
    const float* rem  = (const float*)d_in[2];
    const float* mask = (const float*)d_in[3];
    const float* enc  = (const float*)d_in[4];
    const float* Wq   = (const float*)d_in[5];
    const float* Wk   = (const float*)d_in[6];
    const float* Wv   = (const float*)d_in[7];
    const float* Wc   = (const float*)d_in[8];
    const float* bc   = (const float*)d_in[9];
    float* out = (float*)d_out;

    size_t smem = (size_t)56512 * sizeof(float);  // 226048 B
    cudaFuncSetAttribute(fused_attn_kernel,
                         cudaFuncAttributeMaxDynamicSharedMemorySize, (int)smem);
    fused_attn_kernel<<<NB, NTHR, smem>>>(in1, in2, rem, mask, enc,
                                          Wq, Wk, Wv, Wc, bc, out);
}

// round 6
// speedup vs baseline: 1.5360x; 1.5360x over previous
#include <cuda_runtime.h>

#define NB 512
#define NG 100
#define NP 100
#define NE 128
#define NH 8
#define NKD 16
#define LDP 132     // padded row stride (floats)
#define LDW 132     // WT row stride
#define NTHR 1024

typedef unsigned long long u64;

__device__ __forceinline__ void fma2(u64& d, u64 a, u64 b) {
    asm("fma.rn.f32x2 %0, %1, %2, %0;" : "+l"(d) : "l"(a), "l"(b));
}
__device__ __forceinline__ u64 add2(u64 a, u64 b) {
    u64 d; asm("add.rn.f32x2 %0, %1, %2;" : "=l"(d) : "l"(a), "l"(b)); return d;
}
__device__ __forceinline__ u64 pk(float lo, float hi) {
    u64 d; asm("mov.b64 %0, {%1, %2};" : "=l"(d) : "f"(lo), "f"(hi)); return d;
}
__device__ __forceinline__ float f2sum(u64 a) {
    float lo, hi; asm("mov.b64 {%0, %1}, %2;" : "=f"(lo), "=f"(hi) : "l"(a));
    return lo + hi;
}

// Transpose 128x128 weight into smem WT[n][e]=W[e][n] (1024 threads).
__device__ __forceinline__ void fillWT(const float* __restrict__ W,
                                       float* __restrict__ WT, int t) {
    int n  = t & 127;
    int eb = t >> 7;                 // 0..7, covers e in [16*eb, 16*eb+16)
    #pragma unroll
    for (int pass = 0; pass < 4; ++pass) {
        int e = eb * 16 + pass * 4;
        float4 v;
        v.x = __ldg(W + (e + 0) * NE + n);
        v.y = __ldg(W + (e + 1) * NE + n);
        v.z = __ldg(W + (e + 2) * NE + n);
        v.w = __ldg(W + (e + 3) * NE + n);
        *(float4*)(WT + n * LDW + e) = v;
    }
}

// acc[i] += A[mg*13+i][:] . WT[n][:], e-len 128, f32x2 e-packed.
// Rows mg*13+i up to 103 are read unguarded (in-bounds garbage, discarded at store).
__device__ __forceinline__ void gemm13(const float* __restrict__ A,
                                       const float* __restrict__ WT,
                                       u64 (&acc)[13], int n, int mg) {
    const ulonglong2* wp = (const ulonglong2*)(WT + n * LDW);
    const float* abase = A + mg * 13 * LDP;
    #pragma unroll 2
    for (int e4 = 0; e4 < 32; ++e4) {
        ulonglong2 w = wp[e4];
        const float* ar = abase + e4 * 4;
        #pragma unroll
        for (int i = 0; i < 13; ++i) {
            ulonglong2 a = *(const ulonglong2*)(ar + i * LDP);
            fma2(acc[i], a.x, w.x);
            fma2(acc[i], a.y, w.y);
        }
    }
}

__global__ __launch_bounds__(NTHR, 1)
void fused_attn_kernel(
    const float* __restrict__ in1, const float* __restrict__ in2,
    const float* __restrict__ rem, const float* __restrict__ mask,
    const float* __restrict__ enc, const float* __restrict__ Wq,
    const float* __restrict__ Wk, const float* __restrict__ Wv,
    const float* __restrict__ Wc, const float* __restrict__ bc,
    float* __restrict__ out)
{
    extern __shared__ float sm[];
    // [0,13200)      s_enc  (live to the end)
    // [13200,26400)  s_k    (WT alias spills to 30088) / k / mh
    // [26400,29728)  s_ws   32 x 104
    // [29728,29856)  s_q0
    // [30112,43312)  s_v
    // [43312,56512)  s_q    (+4 garbage rows readable to 57040; alloc 57056)
    float* s_enc = sm;
    float* s_k   = sm + 13200;
    float* s_ws  = sm + 26400;
    float* s_q0  = sm + 29728;
    float* s_v   = sm + 30112;
    float* s_q   = sm + 43312;
    float* s_wt  = s_k;          // alias

    const int b    = blockIdx.x;
    const int t    = threadIdx.x;
    const int lane = t & 31;
    const int warp = t >> 5;             // 0..31
    const int mg   = warp >> 2;          // 0..7  (13 rows each)
    const int n    = (warp & 3) * 32 + lane;

    const float* encb  = enc  + (size_t)b * NP * NE;
    const float* in2b  = in2  + (size_t)b * NG * NE;
    const float* maskb = mask + (size_t)b * NG * NP;
    const float* remb  = rem  + (size_t)b * NG;

    u64 acc[13];

    // ---------------- Phase 1: stage enc + input2, compute q0 ----------------
    for (int idx = t; idx < NP * NE; idx += NTHR)
        s_enc[(idx >> 7) * LDP + (idx & 127)] = encb[idx];
    for (int idx = t; idx < NG * NE; idx += NTHR)
        s_q[(idx >> 7) * LDP + (idx & 127)] = in2b[idx];
    if (t < NE) {
        const float* i1 = in1 + (size_t)b * NE;
        float s = 0.f;
        #pragma unroll 8
        for (int e = 0; e < NE; ++e) s += i1[e] * __ldg(Wq + e * NE + t);
        s_q0[t] = s;
    }
    __syncthreads();                              // S1

    // ---------------- q-pass: q = [in1 | in2 | rem] @ Wq ----------------
    {
        float rq0 = s_q0[n];
        float rwl = __ldg(Wq + 2 * NE * NE + n);  // last row (rem weight)
        __syncthreads();                          // S2: q0 reads done before WT spill
        fillWT(Wq + NE * NE, s_wt, t);            // rows 128..255 (input2 part)
        __syncthreads();                          // S3
        #pragma unroll
        for (int i = 0; i < 13; ++i) acc[i] = 0ull;
        gemm13(s_q, s_wt, acc, n, mg);
        __syncthreads();                          // S4: WT + staged-input2 reads done
        #pragma unroll
        for (int i = 0; i < 13; ++i) {
            int m = mg * 13 + i;
            if (m < NG)
                s_q[m * LDP + n] = f2sum(acc[i]) + rq0 + __ldg(remb + m) * rwl;
        }
    }

    // ---------------- v-pass: v = enc @ Wv ----------------
    fillWT(Wv, s_wt, t);                          // WT reads done at S4
    __syncthreads();                              // S5
    #pragma unroll
    for (int i = 0; i < 13; ++i) acc[i] = 0ull;
    gemm13(s_enc, s_wt, acc, n, mg);
    #pragma unroll
    for (int i = 0; i < 13; ++i) {
        int m = mg * 13 + i;
        if (m < NP) s_v[m * LDP + n] = f2sum(acc[i]);
    }
    __syncthreads();                              // S6

    // ---------------- k-pass: k = enc @ Wk ----------------
    fillWT(Wk, s_wt, t);
    __syncthreads();                              // S7
    #pragma unroll
    for (int i = 0; i < 13; ++i) acc[i] = 0ull;
    gemm13(s_enc, s_wt, acc, n, mg);
    __syncthreads();                              // S8: WT reads done before k overwrites
    #pragma unroll
    for (int i = 0; i < 13; ++i) {
        int m = mg * 13 + i;
        if (m < NP) s_k[m * LDP + n] = f2sum(acc[i]);
    }
    __syncthreads();                              // S9

    // ---------------- Phase 4: multi-head attention ----------------
    for (int task = warp; task < (NG / 2) * NH; task += 32) {
        int h  = task & 7;
        int gp = task >> 3;
        int g0 = 2 * gp, g1 = g0 + 1;
        const ulonglong2* qp0 = (const ulonglong2*)(s_q + g0 * LDP + h * NKD);
        const ulonglong2* qp1 = (const ulonglong2*)(s_q + g1 * LDP + h * NKD);

        // QK in two head-dim halves (keeps q live-set at 16 regs)
        u64 x0[4] = {0,0,0,0}, x1[4] = {0,0,0,0};
        #pragma unroll
        for (int half = 0; half < 2; ++half) {
            ulonglong2 qa0 = qp0[2 * half], qa1 = qp0[2 * half + 1];
            ulonglong2 qb0 = qp1[2 * half], qb1 = qp1[2 * half + 1];
            #pragma unroll
            for (int r = 0; r < 4; ++r) {
                int p = lane + 32 * r;   // p<=127: reads bleed into WT-spill smem (garbage, masked)
                const ulonglong2* kp = (const ulonglong2*)(s_k + p * LDP + h * NKD);
                ulonglong2 k0 = kp[2 * half], k1 = kp[2 * half + 1];
                fma2(x0[r], qa0.x, k0.x); fma2(x0[r], qa0.y, k0.y);
                fma2(x0[r], qa1.x, k1.x); fma2(x0[r], qa1.y, k1.y);
                fma2(x1[r], qb0.x, k0.x); fma2(x1[r], qb0.y, k0.y);
                fma2(x1[r], qb1.x, k1.x); fma2(x1[r], qb1.y, k1.y);
            }
        }

        float s0[4], s1[4];
        float mx0 = -3e38f, mx1 = -3e38f;
        #pragma unroll
        for (int r = 0; r < 4; ++r) {
            int p = lane + 32 * r;
            float a0 = -3e38f, a1 = -3e38f;
            if (p < NP) {
                a0 = f2sum(x0[r]) * 0.25f + __ldg(maskb + g0 * NP + p);
                a1 = f2sum(x1[r]) * 0.25f + __ldg(maskb + g1 * NP + p);
            }
            s0[r] = a0; s1[r] = a1;
            mx0 = fmaxf(mx0, a0); mx1 = fmaxf(mx1, a1);
        }
        #pragma unroll
        for (int o = 16; o; o >>= 1) {
            mx0 = fmaxf(mx0, __shfl_xor_sync(0xffffffffu, mx0, o));
            mx1 = fmaxf(mx1, __shfl_xor_sync(0xffffffffu, mx1, o));
        }
        float sum0 = 0.f, sum1 = 0.f;
        #pragma unroll
        for (int r = 0; r < 4; ++r) {
            float e0 = (s0[r] > -1e37f) ? __expf(s0[r] - mx0) : 0.f;
            float e1 = (s1[r] > -1e37f) ? __expf(s1[r] - mx1) : 0.f;
            s0[r] = e0; s1[r] = e1; sum0 += e0; sum1 += e1;
        }
        #pragma unroll
        for (int o = 16; o; o >>= 1) {
            sum0 += __shfl_xor_sync(0xffffffffu, sum0, o);
            sum1 += __shfl_xor_sync(0xffffffffu, sum1, o);
        }
        float inv0 = 1.f / sum0, inv1 = 1.f / sum1;

        // AV: two per-g passes over one 104-slot ws buffer
        float* w0 = s_ws + warp * 104;
        int c4 = lane >> 3, pgl = lane & 7;
        #pragma unroll
        for (int gsel = 0; gsel < 2; ++gsel) {
            #pragma unroll
            for (int r = 0; r < 4; ++r) {
                int p = lane + 32 * r;
                if (p < NP) w0[p] = gsel ? s1[r] * inv1 : s0[r] * inv0;
            }
            __syncwarp();
            u64 o0 = 0, o1 = 0;
            #pragma unroll
            for (int pp = 0; pp < 13; ++pp) {
                int p = pgl + 8 * pp;
                if (p < NP) {
                    ulonglong2 vv = *((const ulonglong2*)(s_v + p * LDP + h * NKD) + c4);
                    u64 aa = pk(w0[p], w0[p]);
                    fma2(o0, aa, vv.x);
                    fma2(o1, aa, vv.y);
                }
            }
            #pragma unroll
            for (int o = 4; o; o >>= 1) {
                o0 = add2(o0, __shfl_xor_sync(0xffffffffu, o0, o));
                o1 = add2(o1, __shfl_xor_sync(0xffffffffu, o1, o));
            }
            if (pgl == 0) {
                ulonglong2 r0; r0.x = o0; r0.y = o1;
                *((ulonglong2*)(s_q + (gsel ? g1 : g0) * LDP + h * NKD + 4 * c4)) = r0;
            }
            __syncwarp();
        }
    }
    __syncthreads();                              // S10

    // ---------------- Phase 5: mh = out_concat @ Wc + bc -> s_k -------------
    fillWT(Wc, s_wt, t);                          // clobbers k + ws + q0 (all dead)
    __syncthreads();                              // S11
    {
        float rbc = __ldg(bc + n);
        #pragma unroll
        for (int i = 0; i < 13; ++i) acc[i] = 0ull;
        gemm13(s_q, s_wt, acc, n, mg);
        __syncthreads();                          // S12: WT reads done before mh overwrites
        #pragma unroll
        for (int i = 0; i < 13; ++i) {
            int m = mg * 13 + i;
            if (m < NG) s_k[m * LDP + n] = f2sum(acc[i]) + rbc;
        }
    }
    __syncthreads();                              // S13

    // ---------------- Phase 6: pointer scores + clipped softmax -------------
    const float invsq = 0.08838834764831845f;     // 1/sqrt(128)
    float* outb = out + (size_t)b * NG * NP;
    for (int t6 = warp; t6 < NG / 2; t6 += 32) {  // 2 g per task
        int g0 = 2 * t6, g1 = g0 + 1;
        u64 pacc[2][4];
        #pragma unroll
        for (int g = 0; g < 2; ++g)
            #pragma unroll
            for (int r = 0; r < 4; ++r) pacc[g][r] = 0ull;
        const ulonglong2* ep[4];
        #pragma unroll
        for (int r = 0; r < 4; ++r)
            ep[r] = (const ulonglong2*)(s_enc + (lane + 32 * r) * LDP);  // p<=127 in-bounds
        const ulonglong2* mp0 = (const ulonglong2*)(s_k + g0 * LDP);
        const ulonglong2* mp1 = (const ulonglong2*)(s_k + g1 * LDP);
        #pragma unroll 2
        for (int e4 = 0; e4 < 32; ++e4) {
            ulonglong2 m0 = mp0[e4], m1 = mp1[e4];
            #pragma unroll
            for (int r = 0; r < 4; ++r) {
                ulonglong2 ea = ep[r][e4];
                fma2(pacc[0][r], m0.x, ea.x); fma2(pacc[0][r], m0.y, ea.y);
                fma2(pacc[1][r], m1.x, ea.x); fma2(pacc[1][r], m1.y, ea.y);
            }
        }
        #pragma unroll
        for (int g = 0; g < 2; ++g) {
            int gi = g0 + g;
            float sc[4]; float mx = -3e38f;
            #pragma unroll
            for (int r = 0; r < 4; ++r) {
                int p = lane + 32 * r;
                float s = -3e38f;
                if (p < NP)
                    s = 10.f * tanhf(f2sum(pacc[g][r]) * invsq) + __ldg(maskb + gi * NP + p);
                sc[r] = s; mx = fmaxf(mx, s);
            }
            #pragma unroll
            for (int o = 16; o; o >>= 1)
                mx = fmaxf(mx, __shfl_xor_sync(0xffffffffu, mx, o));
            float sum = 0.f;
            #pragma unroll
            for (int r = 0; r < 4; ++r) {
                float e_ = (sc[r] > -1e37f) ? __expf(sc[r] - mx) : 0.f;
                sc[r] = e_; sum += e_;
            }
            #pragma unroll
            for (int o = 16; o; o >>= 1)
                sum += __shfl_xor_sync(0xffffffffu, sum, o);
            float inv = 1.f / sum;
            #pragma unroll
            for (int r = 0; r < 4; ++r) {
                int p = lane + 32 * r;
                if (p < NP) outb[gi * NP + p] = sc[r] * inv;
            }
        }
    }
}

extern "C" void kernel_launch(void* const* d_in, const int* in_sizes, int n_in,
                              void* d_out, int out_size)
{
    const float* in1  = (const float*)d_in[0];
    const float* in2  = (const float*)d_in[1];
    const float* rem  = (const float*)d_in[2];
    const float* mask = (const float*)d_in[3];
    const float* enc  = (const float*)d_in[4];
    const float* Wq   = (const float*)d_in[5];
    const float* Wk   = (const float*)d_in[6];
    const float* Wv   = (const float*)d_in[7];
    const float* Wc   = (const float*)d_in[8];
    const float* bc   = (const float*)d_in[9];
    float* out = (float*)d_out;

    size_t smem = (size_t)57056 * sizeof(float);  // 228224 B (<= 232448 cap)
    cudaFuncSetAttribute(fused_attn_kernel,
                         cudaFuncAttributeMaxDynamicSharedMemorySize, (int)smem);
    fused_attn_kernel<<<NB, NTHR, smem>>>(in1, in2, rem, mask, enc,
                                          Wq, Wk, Wv, Wc, bc, out);
}

// round 7
// speedup vs baseline: 1.8222x; 1.1863x over previous
#include <cuda_runtime.h>

#define NB 512
#define NG 100
#define NP 100
#define NE 128
#define NH 8
#define NKD 16
#define LDP 132
#define LDW 132
#define LDK 102     // kT row stride (floats)
#define NTHR 512

typedef unsigned long long u64;

__device__ __forceinline__ void fma2(u64& d, u64 a, u64 b) {
    asm("fma.rn.f32x2 %0, %1, %2, %0;" : "+l"(d) : "l"(a), "l"(b));
}
__device__ __forceinline__ u64 add2(u64 a, u64 b) {
    u64 d; asm("add.rn.f32x2 %0, %1, %2;" : "=l"(d) : "l"(a), "l"(b)); return d;
}
__device__ __forceinline__ u64 pk(float lo, float hi) {
    u64 d; asm("mov.b64 %0, {%1, %2};" : "=l"(d) : "f"(lo), "f"(hi)); return d;
}
__device__ __forceinline__ void unpk(u64 a, float& lo, float& hi) {
    asm("mov.b64 {%0, %1}, %2;" : "=f"(lo), "=f"(hi) : "l"(a));
}
__device__ __forceinline__ float f2sum(u64 a) {
    float lo, hi; unpk(a, lo, hi); return lo + hi;
}

// Transpose a 128x128 weight matrix into smem: WT[n][e] = W[e][n]
__device__ __forceinline__ void fillWT(const float* __restrict__ W,
                                       float* __restrict__ WT, int t) {
    int n  = t & 127;
    int eb = t >> 7;                 // 0..3
    #pragma unroll
    for (int pass = 0; pass < 8; ++pass) {
        int e = eb * 32 + pass * 4;
        float4 v;
        v.x = __ldg(W + (e + 0) * NE + n);
        v.y = __ldg(W + (e + 1) * NE + n);
        v.z = __ldg(W + (e + 2) * NE + n);
        v.w = __ldg(W + (e + 3) * NE + n);
        *(float4*)(WT + n * LDW + e) = v;
    }
}

// C[m][n] += A[m][:] . WT[n][:], e-length 128, packed f32x2 dots.
// lane -> n in {lane+32j}, warp -> m in {warp+16i, i<7} (rows clamped to 99).
__device__ __forceinline__ void gemm128(const float* __restrict__ A,
                                        const float* __restrict__ WT,
                                        u64 (&acc)[7][4], int lane, int warp) {
    const ulonglong2* wp0 = (const ulonglong2*)(WT + lane * LDW);
    const ulonglong2* wp1 = (const ulonglong2*)(WT + (lane + 32) * LDW);
    const ulonglong2* wp2 = (const ulonglong2*)(WT + (lane + 64) * LDW);
    const ulonglong2* wp3 = (const ulonglong2*)(WT + (lane + 96) * LDW);
    const ulonglong2* ap[7];
    #pragma unroll
    for (int i = 0; i < 7; ++i) {
        int m = warp + 16 * i; if (m > 99) m = 99;   // clamped: result discarded
        ap[i] = (const ulonglong2*)(A + m * LDP);
    }
    #pragma unroll 2
    for (int e4 = 0; e4 < 32; ++e4) {
        ulonglong2 w0 = wp0[e4], w1 = wp1[e4], w2 = wp2[e4], w3 = wp3[e4];
        #pragma unroll
        for (int i = 0; i < 7; ++i) {
            ulonglong2 a = ap[i][e4];
            fma2(acc[i][0], a.x, w0.x); fma2(acc[i][0], a.y, w0.y);
            fma2(acc[i][1], a.x, w1.x); fma2(acc[i][1], a.y, w1.y);
            fma2(acc[i][2], a.x, w2.x); fma2(acc[i][2], a.y, w2.y);
            fma2(acc[i][3], a.x, w3.x); fma2(acc[i][3], a.y, w3.y);
        }
    }
}

__global__ __launch_bounds__(NTHR, 1)
void fused_attn_kernel(
    const float* __restrict__ in1, const float* __restrict__ in2,
    const float* __restrict__ rem, const float* __restrict__ mask,
    const float* __restrict__ enc, const float* __restrict__ Wq,
    const float* __restrict__ Wk, const float* __restrict__ Wv,
    const float* __restrict__ Wc, const float* __restrict__ bc,
    float* __restrict__ out)
{
    extern __shared__ float sm[];
    // [0,13200)      s_enc
    // [13200,26400)  s_k region: WT alias (spills to 30096) / kT (128x102=13056) / mh
    // [26400,29728)  s_ws  (16*208)
    // [29728,29856)  s_q0
    // [30112,43312)  s_v
    // [43312,56512)  s_q
    float* s_enc = sm;
    float* s_k   = sm + 13200;
    float* s_ws  = sm + 26400;
    float* s_q0  = sm + 29728;
    float* s_v   = sm + 30112;
    float* s_q   = sm + 43312;
    float* s_wt  = s_k;          // alias
    float* s_kT  = s_k;          // alias

    const int b    = blockIdx.x;
    const int t    = threadIdx.x;
    const int lane = t & 31;
    const int warp = t >> 5;

    const float* encb  = enc  + (size_t)b * NP * NE;
    const float* in2b  = in2  + (size_t)b * NG * NE;
    const float* maskb = mask + (size_t)b * NG * NP;

    // ---------------- Phase 1: stage enc + input2, compute q0 ----------------
    for (int idx = t; idx < NP * NE; idx += NTHR)
        s_enc[(idx >> 7) * LDP + (idx & 127)] = encb[idx];
    for (int idx = t; idx < NG * NE; idx += NTHR)
        s_q[(idx >> 7) * LDP + (idx & 127)] = in2b[idx];
    if (t < NE) {
        const float* i1 = in1 + (size_t)b * NE;
        float s = 0.f;
        #pragma unroll 8
        for (int e = 0; e < NE; ++e) s += i1[e] * __ldg(Wq + e * NE + t);
        s_q0[t] = s;
    }
    __syncthreads();

    // ---------------- q-pass: q = [in1 | in2 | rem] @ Wq ----------------
    {
        float rq0[4], rwl[4], rrem[7];
        #pragma unroll
        for (int j = 0; j < 4; ++j) {
            int n = lane + 32 * j;
            rq0[j] = s_q0[n];
            rwl[j] = __ldg(Wq + 2 * NE * NE + n);   // last row (rem weight)
        }
        const float* remb = rem + (size_t)b * NG;
        #pragma unroll
        for (int i = 0; i < 7; ++i) {
            int m = warp + 16 * i;
            rrem[i] = (m < NG) ? __ldg(remb + m) : 0.f;
        }
        __syncthreads();                 // q0 reads done before WT clobbers it
        fillWT(Wq + NE * NE, s_wt, t);   // rows 128..255 (input2 part)
        __syncthreads();
        u64 acc[7][4];
        #pragma unroll
        for (int i = 0; i < 7; ++i)
            #pragma unroll
            for (int j = 0; j < 4; ++j)
                acc[i][j] = pk(rq0[j] + rrem[i] * rwl[j], 0.f);
        gemm128(s_q, s_wt, acc, lane, warp);
        __syncthreads();                 // all reads (incl. clamped row 99) done
        #pragma unroll
        for (int i = 0; i < 7; ++i) {
            int m = warp + 16 * i;
            if (m < NG)
                #pragma unroll
                for (int j = 0; j < 4; ++j)
                    s_q[m * LDP + lane + 32 * j] = f2sum(acc[i][j]);
        }
        __syncthreads();
    }

    // ---------------- v-pass: v = enc @ Wv ----------------
    {
        fillWT(Wv, s_wt, t);
        __syncthreads();
        u64 acc[7][4] = {};
        gemm128(s_enc, s_wt, acc, lane, warp);
        #pragma unroll
        for (int i = 0; i < 7; ++i) {
            int m = warp + 16 * i;
            if (m < NP)
                #pragma unroll
                for (int j = 0; j < 4; ++j)
                    s_v[m * LDP + lane + 32 * j] = f2sum(acc[i][j]);
        }
        __syncthreads();
    }

    // ---------------- k-pass: kT[n][m] = (enc @ Wk)^T ----------------
    {
        fillWT(Wk, s_wt, t);
        __syncthreads();
        u64 acc[7][4] = {};
        gemm128(s_enc, s_wt, acc, lane, warp);
        __syncthreads();                 // WkT reads done before kT overwrites it
        #pragma unroll
        for (int i = 0; i < 7; ++i) {
            int m = warp + 16 * i;
            if (m < NP)
                #pragma unroll
                for (int j = 0; j < 4; ++j)
                    s_kT[(lane + 32 * j) * LDK + m] = f2sum(acc[i][j]);
        }
        __syncthreads();
    }

    // ---------------- Phase 4: multi-head attention (4 g x head per task) ----
    for (int task = warp; task < (NG / 4) * NH; task += 16) {
        int h  = task & 7;
        int gb = (task >> 3) * 4;
        const float* kTh = s_kT + (h * NKD) * LDK;

        // QK: p-packed scores; lane owns p = {2l,2l+1} and {64+2l,65+2l}
        u64 a0[4] = {0,0,0,0}, a1[4] = {0,0,0,0};
        #pragma unroll
        for (int e0 = 0; e0 < NKD; e0 += 4) {
            float4 qf[4];
            #pragma unroll
            for (int g = 0; g < 4; ++g)
                qf[g] = *(const float4*)(s_q + (gb + g) * LDP + h * NKD + e0);
            #pragma unroll
            for (int e = 0; e < 4; ++e) {
                const float* kr = kTh + (e0 + e) * LDK;
                u64 k0 = *(const u64*)(kr + 2 * lane);
                u64 k1 = *(const u64*)(kr + 64 + 2 * lane);   // lane>=19: in-bounds garbage, masked
                #pragma unroll
                for (int g = 0; g < 4; ++g) {
                    float qv = (e == 0) ? qf[g].x : (e == 1) ? qf[g].y
                             : (e == 2) ? qf[g].z : qf[g].w;
                    u64 q2 = pk(qv, qv);
                    fma2(a0[g], q2, k0);
                    fma2(a1[g], q2, k1);
                }
            }
        }

        // softmax per g (4 scores per lane)
        float w[4][4];
        #pragma unroll
        for (int g = 0; g < 4; ++g) {
            int gi = gb + g;
            float x0, x1, x2, x3;
            unpk(a0[g], x0, x1);
            unpk(a1[g], x2, x3);
            float2 mA = *(const float2*)(maskb + gi * NP + 2 * lane);
            x0 = x0 * 0.25f + mA.x;
            x1 = x1 * 0.25f + mA.y;
            if (lane < 18) {
                float2 mB = *(const float2*)(maskb + gi * NP + 64 + 2 * lane);
                x2 = x2 * 0.25f + mB.x;
                x3 = x3 * 0.25f + mB.y;
            } else { x2 = -3e38f; x3 = -3e38f; }
            float mx = fmaxf(fmaxf(x0, x1), fmaxf(x2, x3));
            #pragma unroll
            for (int o = 16; o; o >>= 1)
                mx = fmaxf(mx, __shfl_xor_sync(0xffffffffu, mx, o));
            x0 = __expf(x0 - mx);
            x1 = __expf(x1 - mx);
            x2 = (lane < 18) ? __expf(x2 - mx) : 0.f;
            x3 = (lane < 18) ? __expf(x3 - mx) : 0.f;
            float sum = x0 + x1 + x2 + x3;
            #pragma unroll
            for (int o = 16; o; o >>= 1)
                sum += __shfl_xor_sync(0xffffffffu, sum, o);
            float inv = 1.f / sum;
            w[g][0] = x0 * inv; w[g][1] = x1 * inv;
            w[g][2] = x2 * inv; w[g][3] = x3 * inv;
        }

        // AV in 2 sub-batches of 2 g via the per-warp ws slot
        float* wsl = s_ws + warp * 208;
        int c4 = lane >> 3, pgl = lane & 7;
        #pragma unroll
        for (int sb = 0; sb < 2; ++sb) {
            int ga = 2 * sb, gbd = 2 * sb + 1;
            float* w0 = wsl;
            float* w1 = wsl + 104;
            *(float2*)(w0 + 2 * lane) = make_float2(w[ga][0], w[ga][1]);
            *(float2*)(w1 + 2 * lane) = make_float2(w[gbd][0], w[gbd][1]);
            if (lane < 18) {
                *(float2*)(w0 + 64 + 2 * lane) = make_float2(w[ga][2], w[ga][3]);
                *(float2*)(w1 + 64 + 2 * lane) = make_float2(w[gbd][2], w[gbd][3]);
            }
            __syncwarp();
            u64 o00 = 0, o01 = 0, o10 = 0, o11 = 0;
            #pragma unroll
            for (int pp = 0; pp < 13; ++pp) {
                int p = pgl + 8 * pp;
                if (p < NP) {
                    ulonglong2 vv = *((const ulonglong2*)(s_v + p * LDP + h * NKD) + c4);
                    u64 aa = pk(w0[p], w0[p]);
                    u64 cc = pk(w1[p], w1[p]);
                    fma2(o00, aa, vv.x); fma2(o01, aa, vv.y);
                    fma2(o10, cc, vv.x); fma2(o11, cc, vv.y);
                }
            }
            #pragma unroll
            for (int o = 4; o; o >>= 1) {
                o00 = add2(o00, __shfl_xor_sync(0xffffffffu, o00, o));
                o01 = add2(o01, __shfl_xor_sync(0xffffffffu, o01, o));
                o10 = add2(o10, __shfl_xor_sync(0xffffffffu, o10, o));
                o11 = add2(o11, __shfl_xor_sync(0xffffffffu, o11, o));
            }
            if (pgl == 0) {
                ulonglong2 r0; r0.x = o00; r0.y = o01;
                ulonglong2 r1; r1.x = o10; r1.y = o11;
                *((ulonglong2*)(s_q + (gb + ga)  * LDP + h * NKD + 4 * c4)) = r0;
                *((ulonglong2*)(s_q + (gb + gbd) * LDP + h * NKD + 4 * c4)) = r1;
            }
            __syncwarp();
        }
    }
    __syncthreads();

    // ---------------- Phase 5: mh = out_concat @ Wc + bc -> s_k ----------------
    {
        fillWT(Wc, s_wt, t);            // clobbers kT (dead) + ws (dead)
        __syncthreads();
        float rbc[4];
        #pragma unroll
        for (int j = 0; j < 4; ++j) rbc[j] = __ldg(bc + lane + 32 * j);
        u64 acc[7][4];
        #pragma unroll
        for (int i = 0; i < 7; ++i)
            #pragma unroll
            for (int j = 0; j < 4; ++j) acc[i][j] = pk(rbc[j], 0.f);
        gemm128(s_q, s_wt, acc, lane, warp);
        __syncthreads();                 // WcT reads done before mh overwrites it
        #pragma unroll
        for (int i = 0; i < 7; ++i) {
            int m = warp + 16 * i;
            if (m < NG)
                #pragma unroll
                for (int j = 0; j < 4; ++j)
                    s_k[m * LDP + lane + 32 * j] = f2sum(acc[i][j]);
        }
        __syncthreads();
    }

    // ---------------- Phase 6: pointer scores + clipped softmax ----------------
    const float invsq = 0.08838834764831845f;   // 1/sqrt(128)
    float* outb = out + (size_t)b * NG * NP;
    for (int t6 = warp; t6 < 25; t6 += 16) {    // 4 g per warp-task
        int g0 = t6 * 4;
        u64 acc[4][4];
        #pragma unroll
        for (int gg = 0; gg < 4; ++gg)
            #pragma unroll
            for (int r = 0; r < 4; ++r) acc[gg][r] = 0ull;
        const ulonglong2* ep[4];
        #pragma unroll
        for (int r = 0; r < 4; ++r)
            ep[r] = (const ulonglong2*)(s_enc + (lane + 32 * r) * LDP);  // p<=127 in-bounds
        const ulonglong2* mp[4];
        #pragma unroll
        for (int gg = 0; gg < 4; ++gg)
            mp[gg] = (const ulonglong2*)(s_k + (g0 + gg) * LDP);
        #pragma unroll 2
        for (int e4 = 0; e4 < 32; ++e4) {
            ulonglong2 m0 = mp[0][e4], m1 = mp[1][e4], m2 = mp[2][e4], m3 = mp[3][e4];
            #pragma unroll
            for (int r = 0; r < 4; ++r) {
                ulonglong2 ea = ep[r][e4];
                fma2(acc[0][r], m0.x, ea.x); fma2(acc[0][r], m0.y, ea.y);
                fma2(acc[1][r], m1.x, ea.x); fma2(acc[1][r], m1.y, ea.y);
                fma2(acc[2][r], m2.x, ea.x); fma2(acc[2][r], m2.y, ea.y);
                fma2(acc[3][r], m3.x, ea.x); fma2(acc[3][r], m3.y, ea.y);
            }
        }
        #pragma unroll
        for (int gg = 0; gg < 4; ++gg) {
            int g = g0 + gg;
            float sc[4]; float mx = -3e38f;
            #pragma unroll
            for (int r = 0; r < 4; ++r) {
                int p = lane + 32 * r;
                float s = -3e38f;
                if (p < NP)
                    s = 10.f * tanhf(f2sum(acc[gg][r]) * invsq) + __ldg(maskb + g * NP + p);
                sc[r] = s; mx = fmaxf(mx, s);
            }
            #pragma unroll
            for (int o = 16; o; o >>= 1) mx = fmaxf(mx, __shfl_xor_sync(0xffffffffu, mx, o));
            float sum = 0.f;
            #pragma unroll
            for (int r = 0; r < 4; ++r) {
                float e_ = (sc[r] > -1e37f) ? __expf(sc[r] - mx) : 0.f;
                sc[r] = e_; sum += e_;
            }
            #pragma unroll
            for (int o = 16; o; o >>= 1) sum += __shfl_xor_sync(0xffffffffu, sum, o);
            float inv = 1.f / sum;
            #pragma unroll
            for (int r = 0; r < 4; ++r) {
                int p = lane + 32 * r;
                if (p < NP) outb[g * NP + p] = sc[r] * inv;
            }
        }
    }
}

extern "C" void kernel_launch(void* const* d_in, const int* in_sizes, int n_in,
                              void* d_out, int out_size)
{
    const float* in1  = (const float*)d_in[0];
    const float* in2  = (const float*)d_in[1];
    const float* rem  = (const float*)d_in[2];
    const float* mask = (const float*)d_in[3];
    const float* enc  = (const float*)d_in[4];
    const float* Wq   = (const float*)d_in[5];
    const float* Wk   = (const float*)d_in[6];
    const float* Wv   = (const float*)d_in[7];
    const float* Wc   = (const float*)d_in[8];
    const float* bc   = (const float*)d_in[9];
    float* out = (float*)d_out;

    size_t smem = (size_t)56512 * sizeof(float);  // 226048 B
    cudaFuncSetAttribute(fused_attn_kernel,
                         cudaFuncAttributeMaxDynamicSharedMemorySize, (int)smem);
    fused_attn_kernel<<<NB, NTHR, smem>>>(in1, in2, rem, mask, enc,
                                          Wq, Wk, Wv, Wc, bc, out);
}